// round 5
// baseline (speedup 1.0000x reference)
#include <cuda_runtime.h>
#include <cuda_bf16.h>
#include <cstdint>

// ---------------- problem constants ----------------
#define NPTS   512            // batch N
#define TT     300            // time steps
#define FF     150            // feature dim
#define HH     100            // hidden dim
#define G4     400            // 4*H gate rows
// x layout strides (floats): x[n][c][t][v][m], C=3,V=25,M=2
#define XSTR_N 45000
#define XSTR_C 15000
#define XSTR_T 50

// ---------------- scratch (device globals; no allocs allowed) ----------------
__device__ float g_Xp[(size_t)TT * NPTS * G4];       // encoder pre-activations (+bias)
__device__ float g_Hs[(size_t)(TT - 1) * NPTS * HH]; // decoder hidden states
__device__ float g_Wt[FF * G4];                      // enc_Wih transposed [f][g]
__device__ float g_Wd[G4 * HH];                      // folded decoder recurrent matrix
__device__ float g_biase[G4];
__device__ float g_bias0[G4];
__device__ float g_biasd[G4];

// ---------------- helpers ----------------
__device__ __forceinline__ void ffma2(float2& c, const float2& a, const float2& b) {
    asm("fma.rn.f32x2 %0, %1, %2, %0;"
        : "+l"(reinterpret_cast<unsigned long long&>(c))
        : "l"(reinterpret_cast<const unsigned long long&>(a)),
          "l"(reinterpret_cast<const unsigned long long&>(b)));
}

__device__ __forceinline__ float sigm(float x) {
    return __fdividef(1.0f, 1.0f + __expf(-x));
}
__device__ __forceinline__ float tanh_(float x) {
    return __fdividef(2.0f, 1.0f + __expf(-2.0f * x)) - 1.0f;
}

// ---------------- prep 1: transpose enc_Wih, build biases ----------------
__global__ void prep_misc_kernel(const float* __restrict__ encWih,
                                 const float* __restrict__ encbih,
                                 const float* __restrict__ encbhh,
                                 const float* __restrict__ decWih,
                                 const float* __restrict__ decbih,
                                 const float* __restrict__ decbhh,
                                 const float* __restrict__ fcb) {
    const int gg  = blockIdx.x;   // gate row 0..399
    const int tid = threadIdx.x;  // 160 threads
    if (tid < FF) g_Wt[tid * G4 + gg] = encWih[gg * FF + tid];
    __shared__ float red[160];
    red[tid] = (tid < FF) ? decWih[gg * FF + tid] * fcb[tid] : 0.0f;
    __syncthreads();
    if (tid == 0) {
        float sum = 0.0f;
        for (int f = 0; f < FF; f++) sum += red[f];
        g_biase[gg] = encbih[gg] + encbhh[gg];
        float b0 = decbih[gg] + decbhh[gg];
        g_bias0[gg] = b0;
        g_biasd[gg] = b0 + sum;
    }
}

// ---------------- prep 2: Wd = dec_Whh + dec_Wih @ fc_W ----------------
__global__ void prep_wd_kernel(const float* __restrict__ decWih,
                               const float* __restrict__ decWhh,
                               const float* __restrict__ fcW) {
    const int gg = blockIdx.x;   // 0..399
    const int h  = threadIdx.x;  // 128 threads
    if (h < HH) {
        float acc = decWhh[gg * HH + h];
        for (int f = 0; f < FF; f++)
            acc += decWih[gg * FF + f] * fcW[f * HH + h];
        g_Wd[gg * HH + h] = acc;
    }
}

// ---------------- xproj: Xp[t*512+n][g] = xs[n,t,:] @ enc_Wih[g,:].T + biase[g] ----------------
// 512 threads, 80-row tiles, double-buffered W chunks (25 k each).
#define XP_NT    80
#define XP_NTP   82            // even pad -> float4-aligned A loads
#define XP_KC    25
#define XP_NCH   6
#define XP_CHF   (XP_KC * G4)  // floats per chunk = 10000
#define XP_SMEM  (150 * XP_NTP * 8 + 2 * XP_CHF * 4)  // 98400 + 80000 = 178400 B

__global__ void __launch_bounds__(512, 1) xproj_kernel(const float* __restrict__ x) {
    extern __shared__ float sm[];
    float2* Adup = reinterpret_cast<float2*>(sm);        // [150][XP_NTP] (value duplicated)
    float*  Wbuf = sm + 150 * XP_NTP * 2;                // [2][XP_CHF]

    const int tid = threadIdx.x;
    const int nt0 = blockIdx.x * XP_NT;

    // stage A (x gather), duplicated into both f32x2 lanes
    for (int idx = tid; idx < XP_NT * FF; idx += 512) {
        int row = idx / FF, f = idx % FF;
        int nt = nt0 + row;
        int n = nt & 511, t = nt >> 9;
        float v = x[(size_t)n * XSTR_N + (f / 50) * XSTR_C + t * XSTR_T + (f % 50)];
        Adup[f * XP_NTP + row] = make_float2(v, v);
    }
    // stage W chunk 0
    {
        const float4* src = reinterpret_cast<const float4*>(g_Wt);
        float4* dst = reinterpret_cast<float4*>(Wbuf);
        #pragma unroll
        for (int i2 = 0; i2 < 5; i2++) {
            int idx = tid + i2 * 512;
            if (idx < XP_CHF / 4) dst[idx] = src[idx];
        }
    }
    __syncthreads();

    const bool act = tid < 500;
    const int gi = tid % 25;   // g-pair base: g = 2*gi + 50*j
    const int ni = tid / 25;   // rows ni*4 .. ni*4+3  (ni 0..19 active)

    float2 acc[4][8];
    #pragma unroll
    for (int r = 0; r < 4; r++)
        #pragma unroll
        for (int j = 0; j < 8; j++) acc[r][j] = make_float2(0.f, 0.f);

    for (int c = 0; c < XP_NCH; c++) {
        // prefetch next chunk into registers (latency hidden under compute)
        float4 pf[5];
        const bool has = (c + 1 < XP_NCH);
        if (has) {
            const float4* src = reinterpret_cast<const float4*>(g_Wt + (c + 1) * XP_CHF);
            #pragma unroll
            for (int i2 = 0; i2 < 5; i2++) {
                int idx = tid + i2 * 512;
                pf[i2] = (idx < XP_CHF / 4) ? src[idx] : make_float4(0.f, 0.f, 0.f, 0.f);
            }
        }
        const float* Wc = Wbuf + (c & 1) * XP_CHF;
        if (act) {
            #pragma unroll
            for (int k = 0; k < XP_KC; k++) {
                const float4 a01 = *reinterpret_cast<const float4*>(
                    &Adup[(c * XP_KC + k) * XP_NTP + ni * 4]);
                const float4 a23 = *reinterpret_cast<const float4*>(
                    &Adup[(c * XP_KC + k) * XP_NTP + ni * 4 + 2]);
                float2 a0 = make_float2(a01.x, a01.y);
                float2 a1 = make_float2(a01.z, a01.w);
                float2 a2 = make_float2(a23.x, a23.y);
                float2 a3 = make_float2(a23.z, a23.w);
                #pragma unroll
                for (int j = 0; j < 8; j++) {
                    float2 w = *reinterpret_cast<const float2*>(&Wc[k * G4 + 2 * gi + 50 * j]);
                    ffma2(acc[0][j], a0, w);
                    ffma2(acc[1][j], a1, w);
                    ffma2(acc[2][j], a2, w);
                    ffma2(acc[3][j], a3, w);
                }
            }
        }
        if (has) {
            float4* dst = reinterpret_cast<float4*>(Wbuf + ((c + 1) & 1) * XP_CHF);
            #pragma unroll
            for (int i2 = 0; i2 < 5; i2++) {
                int idx = tid + i2 * 512;
                if (idx < XP_CHF / 4) dst[idx] = pf[i2];
            }
        }
        __syncthreads();
    }

    if (act) {
        #pragma unroll
        for (int r = 0; r < 4; r++) {
            size_t base = (size_t)(nt0 + ni * 4 + r) * G4;
            #pragma unroll
            for (int j = 0; j < 8; j++) {
                int gg = 2 * gi + 50 * j;
                float2 o = acc[r][j];
                o.x += g_biase[gg];
                o.y += g_biase[gg + 1];
                *reinterpret_cast<float2*>(&g_Xp[base + gg]) = o;
            }
        }
    }
}

// ---------------- recurrence: 128 CTAs x 4 samples, 599 serial steps ----------------
// Lane map: l = j4*8 + type*2 + khalf (j4 = j within warp's 4 units).
// Thread (jj, type, khalf) holds half the W row of gate = type*100+jj (13 float4).
// khalf-reduce: 4x shfl.xor(1). Gate gather: shfl.xor(2/4/6) brings f,g,o to the
// i-lane (same warp!). ONE barrier per step, Hsm double-buffered.
__global__ void __launch_bounds__(800, 1) recur_kernel(const float* __restrict__ encWhh,
                                                       const float* __restrict__ decWhh) {
    __shared__ __align__(16) float Hsm[2][4][104];   // double-buffered, pad [100..104)=0

    const int tid   = threadIdx.x;       // 0..799
    const int l     = tid & 31;
    const int w     = tid >> 5;          // 0..24
    const int jj    = w * 4 + (l >> 3);  // hidden unit 0..99
    const int type  = (l >> 1) & 3;      // 0=i 1=f 2=g 3=o
    const int khalf = l & 1;
    const int gate  = type * 100 + jj;
    const int b0    = khalf * 13;
    const int s0    = khalf * 2;
    const int s1    = s0 + 1;
    const int n0    = blockIdx.x * 4;
    const bool is_i = (type == 0);
    const float ascale = (type == 2) ? 2.0f : 1.0f;   // tanh(x)=2*sigm(2x)-1

    float4 W4[13];
    float c0r = 0.0f, c1r = 0.0f;

    // zero both Hsm buffers (2*4*104 = 832 floats)
    reinterpret_cast<float*>(Hsm)[tid] = 0.0f;
    if (tid < 32) reinterpret_cast<float*>(Hsm)[800 + tid] = 0.0f;

    auto load_w = [&](const float* Wrow) {
        #pragma unroll
        for (int b = 0; b < 13; b++) {
            int k0 = (b0 + b) * 4;
            if (k0 < HH)
                W4[b] = *reinterpret_cast<const float4*>(Wrow + k0);
            else
                W4[b] = make_float4(0.f, 0.f, 0.f, 0.f);
        }
    };

    load_w(encWhh + gate * HH);
    __syncthreads();

    int p = 0;

    auto step = [&](float x0, float x1, bool store_h, int k) {
        float2 acc[4];
        #pragma unroll
        for (int s = 0; s < 4; s++) acc[s] = make_float2(0.f, 0.f);

        #pragma unroll
        for (int b = 0; b < 13; b++) {
            float4 wv = W4[b];
            float2 wlo = make_float2(wv.x, wv.y);
            float2 whi = make_float2(wv.z, wv.w);
            const int off = (b0 + b) * 4;
            #pragma unroll
            for (int s = 0; s < 4; s++) {
                float4 h = *reinterpret_cast<const float4*>(&Hsm[p][s][off]);
                ffma2(acc[s], wlo, make_float2(h.x, h.y));
                ffma2(acc[s], whi, make_float2(h.z, h.w));
            }
        }

        // cross-khalf reduction: full dot for all 4 samples (valid in both lanes)
        float full[4];
        #pragma unroll
        for (int s = 0; s < 4; s++) {
            float v = acc[s].x + acc[s].y;
            full[s] = v + __shfl_xor_sync(0xFFFFFFFFu, v, 1);
        }

        // activate my two samples (branch-free sigmoid/tanh)
        float a0 = ascale * sigm(ascale * (full[s0] + x0)) - (ascale - 1.0f);
        float a1 = ascale * sigm(ascale * (full[s1] + x1)) - (ascale - 1.0f);

        // gather f,g,o into the i-lane (same khalf preserved)
        float f0 = __shfl_xor_sync(0xFFFFFFFFu, a0, 2);
        float g0 = __shfl_xor_sync(0xFFFFFFFFu, a0, 4);
        float o0 = __shfl_xor_sync(0xFFFFFFFFu, a0, 6);
        float f1 = __shfl_xor_sync(0xFFFFFFFFu, a1, 2);
        float g1 = __shfl_xor_sync(0xFFFFFFFFu, a1, 4);
        float o1 = __shfl_xor_sync(0xFFFFFFFFu, a1, 6);

        if (is_i) {
            c0r = f0 * c0r + a0 * g0;
            c1r = f1 * c1r + a1 * g1;
            float h0 = o0 * (2.0f * sigm(2.0f * c0r) - 1.0f);
            float h1 = o1 * (2.0f * sigm(2.0f * c1r) - 1.0f);
            Hsm[p ^ 1][s0][jj] = h0;
            Hsm[p ^ 1][s1][jj] = h1;
            if (store_h) {
                g_Hs[((size_t)k * NPTS + n0 + s0) * HH + jj] = h0;
                g_Hs[((size_t)k * NPTS + n0 + s1) * HH + jj] = h1;
            }
        }
        __syncthreads();
        p ^= 1;
    };

    // ---- encoder: 300 steps, g_Xp prefetched one step ahead ----
    float px0, px1;
    {
        const float* pp = g_Xp + ((size_t)0 * NPTS + n0) * G4 + gate;
        px0 = pp[(size_t)s0 * G4];
        px1 = pp[(size_t)s1 * G4];
    }
    for (int t = 0; t < TT; t++) {
        float cx0 = px0, cx1 = px1;
        if (t + 1 < TT) {
            const float* pp = g_Xp + ((size_t)(t + 1) * NPTS + n0) * G4 + gate;
            px0 = pp[(size_t)s0 * G4];
            px1 = pp[(size_t)s1 * G4];
        }
        step(cx0, cx1, false, 0);
    }

    // ---- decoder step 0: raw dec_Whh (inp = 0) ----
    load_w(decWhh + gate * HH);
    {
        float b = g_bias0[gate];
        step(b, b, true, 0);
    }

    // ---- decoder steps 1..298: folded Wd ----
    load_w(g_Wd + gate * HH);
    {
        float b = g_biasd[gate];
        for (int k = 1; k < TT - 1; k++)
            step(b, b, true, k);
    }
}

// ---------------- zero out t=0 slice of the output ----------------
__global__ void zero_t0_kernel(float* __restrict__ out) {
    int idx = blockIdx.x * 256 + threadIdx.x;
    if (idx < NPTS * FF) {
        int n = idx / FF, f = idx % FF;
        out[(size_t)n * XSTR_N + (f / 50) * XSTR_C + (f % 50)] = 0.0f;
    }
}

// ---------------- fc: out[t>=1] = Hs @ fc_W.T + fc_b, scattered to (N,C,T,V,M) ----------------
#define FC_ROWS 32
#define FC_WPAD 102
#define FC_SMEM ((FF * FC_WPAD + FC_ROWS * HH) * 4)  // 61200 + 12800 = 74000 B

__global__ void __launch_bounds__(320, 2) fc_kernel(const float* __restrict__ fcW,
                                                    const float* __restrict__ fcb,
                                                    float* __restrict__ out) {
    extern __shared__ float sm[];
    float* fcWs = sm;                 // [150][FC_WPAD]
    float* hs   = sm + FF * FC_WPAD;  // [32][100]

    const int tid = threadIdx.x;  // 320
    const int d0  = blockIdx.x * FC_ROWS;

    for (int idx = tid; idx < FF * HH; idx += 320) {
        int f = idx / HH, h = idx % HH;
        fcWs[f * FC_WPAD + h] = fcW[idx];
    }
    for (int idx = tid; idx < FC_ROWS * HH; idx += 320) {
        int r = idx / HH, h = idx % HH;
        hs[r * HH + h] = g_Hs[(size_t)(d0 + r) * HH + h];
    }
    __syncthreads();

    if (tid < 300) {
        const int rg = tid / 75;
        const int f  = 2 * (tid % 75);
        float2 acc[2][8];
        #pragma unroll
        for (int a = 0; a < 2; a++)
            #pragma unroll
            for (int r = 0; r < 8; r++) acc[a][r] = make_float2(0.f, 0.f);

        #pragma unroll
        for (int h2 = 0; h2 < 50; h2++) {
            float2 wa = *reinterpret_cast<const float2*>(&fcWs[f * FC_WPAD + 2 * h2]);
            float2 wb = *reinterpret_cast<const float2*>(&fcWs[(f + 1) * FC_WPAD + 2 * h2]);
            #pragma unroll
            for (int r = 0; r < 8; r++) {
                float2 hv = *reinterpret_cast<const float2*>(&hs[(rg * 8 + r) * HH + 2 * h2]);
                ffma2(acc[0][r], wa, hv);
                ffma2(acc[1][r], wb, hv);
            }
        }

        float b0 = fcb[f], b1 = fcb[f + 1];
        int c = f / 50, rr = f % 50;
        #pragma unroll
        for (int r = 0; r < 8; r++) {
            int d = d0 + rg * 8 + r;
            int n = d & 511;
            int t = (d >> 9) + 1;
            float2 o = make_float2(acc[0][r].x + acc[0][r].y + b0,
                                   acc[1][r].x + acc[1][r].y + b1);
            *reinterpret_cast<float2*>(&out[(size_t)n * XSTR_N + c * XSTR_C + t * XSTR_T + rr]) = o;
        }
    }
}

// ---------------- launch ----------------
extern "C" void kernel_launch(void* const* d_in, const int* in_sizes, int n_in,
                              void* d_out, int out_size) {
    const float* x       = (const float*)d_in[0];
    const float* encWih  = (const float*)d_in[1];
    const float* encWhh  = (const float*)d_in[2];
    const float* encbih  = (const float*)d_in[3];
    const float* encbhh  = (const float*)d_in[4];
    const float* decWih  = (const float*)d_in[5];
    const float* decWhh  = (const float*)d_in[6];
    const float* decbih  = (const float*)d_in[7];
    const float* decbhh  = (const float*)d_in[8];
    const float* fcW     = (const float*)d_in[9];
    const float* fcb     = (const float*)d_in[10];
    float* out = (float*)d_out;
    (void)in_sizes; (void)n_in; (void)out_size;

    cudaFuncSetAttribute(xproj_kernel, cudaFuncAttributeMaxDynamicSharedMemorySize, XP_SMEM);
    cudaFuncSetAttribute(fc_kernel,    cudaFuncAttributeMaxDynamicSharedMemorySize, FC_SMEM);

    prep_misc_kernel<<<G4, 160>>>(encWih, encbih, encbhh, decWih, decbih, decbhh, fcb);
    prep_wd_kernel<<<G4, 128>>>(decWih, decWhh, fcW);

    xproj_kernel<<<(TT * NPTS) / XP_NT, 512, XP_SMEM>>>(x);           // 1920 blocks
    recur_kernel<<<NPTS / 4, 800>>>(encWhh, decWhh);                  // 128 blocks, 1 wave
    zero_t0_kernel<<<(NPTS * FF + 255) / 256, 256>>>(out);
    fc_kernel<<<((TT - 1) * NPTS) / FC_ROWS, 320, FC_SMEM>>>(fcW, fcb, out);  // 4784 blocks
}